// round 6
// baseline (speedup 1.0000x reference)
#include <cuda_runtime.h>
#include <stdint.h>

#define D_DIM   10000
#define T_STEPS 2048
#define TN      2046            /* ngram terms */
#define ROWPW   2512            /* padded table row: 10048 cols = 2512 words */
#define GROUPS  81              /* column groups, stride 124, window 128 */
#define SSPLIT  5               /* t-splits per group */
#define TCHUNK  410             /* ceil(2046/5) */
#define WCH     26              /* ceil(410/16) steps per warp */
#define IDXN    412             /* staged idx entries per block */
#define NG_WORDS (12800 + 128 + IDXN*4)
#define NG_SMEM  (NG_WORDS * 4)

#define TABW_THREADS 125600     /* 100 rows x 1256 word-pairs */
#define TABW_BLOCKS  491
#define AUX_BLOCKS   40         /* zero g_sample + idx pack */

/* {0,1} tables: row = c*100+l, padded 10048 cols (cols>=10000 mirror 0..47) */
__device__ uint32_t g_tab[400 * ROWPW];
__device__ uint4    g_idx4[T_STEPS];      /* per-t smem word offsets, 4 channels */
__device__ float    g_sample[D_DIM];
__device__ float    g_comb[D_DIM];

__constant__ int c_featIdx[29] = {
    546,547,548,550,553,555,556,557,558,559,560,561,562,564,
    565,566,569,575,579,580,581,582,583,584,587,592,597,598,599
};

/* ---------- kernel 1: table build + zero + level-index pack ---------- */
__global__ void __launch_bounds__(256) k_init(const float* __restrict__ signals,
                                              const float* __restrict__ keys,
                                              const float* __restrict__ lw)
{
    const int bid = blockIdx.x;
    const int tid = threadIdx.x;

    if (bid < TABW_BLOCKS) {
        const int j = bid * 256 + tid;
        if (j >= TABW_THREADS) return;
        const int l  = j / 1256;
        const int wp = j - l * 1256;
        const int w  = 2 * wp;
        const int dd = 4 * w;
        const int dsrc = (dd >= D_DIM) ? dd - D_DIM : dd;   /* pair never straddles */

        const float4 wfA = *(const float4*)(lw + l * D_DIM + dsrc);
        const float4 wfB = *(const float4*)(lw + l * D_DIM + dsrc + 4);
        const uint32_t wa0 = __float_as_uint(wfA.x), wa1 = __float_as_uint(wfA.y);
        const uint32_t wa2 = __float_as_uint(wfA.z), wa3 = __float_as_uint(wfA.w);
        const uint32_t wb0 = __float_as_uint(wfB.x), wb1 = __float_as_uint(wfB.y);
        const uint32_t wb2 = __float_as_uint(wfB.z), wb3 = __float_as_uint(wfB.w);

#pragma unroll
        for (int c = 0; c < 4; ++c) {
            const float4 kfA = *(const float4*)(keys + c * D_DIM + dsrc);
            const float4 kfB = *(const float4*)(keys + c * D_DIM + dsrc + 4);
            uint2 p;
            p.x = ((~(__float_as_uint(kfA.x) ^ wa0)) >> 31)
                | (((~(__float_as_uint(kfA.y) ^ wa1)) >> 31) << 8)
                | (((~(__float_as_uint(kfA.z) ^ wa2)) >> 31) << 16)
                | (((~(__float_as_uint(kfA.w) ^ wa3)) >> 31) << 24);
            p.y = ((~(__float_as_uint(kfB.x) ^ wb0)) >> 31)
                | (((~(__float_as_uint(kfB.y) ^ wb1)) >> 31) << 8)
                | (((~(__float_as_uint(kfB.z) ^ wb2)) >> 31) << 16)
                | (((~(__float_as_uint(kfB.w) ^ wb3)) >> 31) << 24);
            *(uint2*)(g_tab + (c * 100 + l) * ROWPW + w) = p;
        }
    } else {
        const int i = (bid - TABW_BLOCKS) * 256 + tid;
        if (i < D_DIM) g_sample[i] = 0.0f;
        if (i < T_STEPS) {
            int l[4];
#pragma unroll
            for (int c = 0; c < 4; ++c) {
                float s = signals[i * 4 + c];
                s = fminf(fmaxf(s, 0.0f), 1.0f);
                int v = (int)rintf(s * 99.0f);    /* round-half-even == jnp.round */
                l[c] = min(max(v, 0), 99);
            }
            g_idx4[i] = make_uint4(l[0]*32, 3200 + l[1]*32, 6400 + l[2]*32, 9600 + l[3]*32);
        }
    }
}

/* ---------- kernel 2: per_t + ngram + multiset sum ---------- */
__global__ void __launch_bounds__(512) k_ngram()
{
    extern __shared__ uint32_t smem[];
    uint32_t* s_tab = smem;                          /* 12800 words */
    int*      s_acc = (int*)(smem + 12800);          /* 128 accumulators */
    uint4*    s_idx = (uint4*)(smem + 12800 + 128);  /* IDXN uint4 */

    const int tid = threadIdx.x;
    const int g   = blockIdx.x / SSPLIT;
    const int s   = blockIdx.x % SSPLIT;
    const int gw  = g * 31;                          /* window start, words */
    const int tb  = s * TCHUNK;

    for (int w = tid; w < 12800; w += 512)
        s_tab[w] = g_tab[(w >> 5) * ROWPW + gw + (w & 31)];
    if (tid < 128) s_acc[tid] = 0;
    if (tid < IDXN) {
        const int t = tb + tid;
        if (t < T_STEPS) s_idx[tid] = g_idx4[t];
    }
    __syncthreads();

    const int warp = tid >> 5;
    const int lane = tid & 31;
    const int t0 = tb + warp * WCH;
    const int i1 = min(min(t0 + WCH, tb + TCHUNK), TN);

    if (t0 < i1) {
        int a2x, a2y, a2z, a2w;             /* s2 @ t-2 */
        int b2x, b2y, b2z, b2w;             /* s2 @ t-1 */
        int b1x, b1y, b1z, b1w;             /* s1 @ t-1 */
        int ax = 0, ay = 0, az = 0, aw = 0;

        /* per_t = 2s-4; carry v = s-2 (dp4a acc -2); x8 restored at writeback */
#define NG_STEP(LI, V0,V1,V2,V3, S1X,S1Y,S1Z,S1W, S2X,S2Y,S2Z,S2W)             \
        {                                                                       \
            const uint4 ix = s_idx[LI];                                         \
            const uint32_t u0 = s_tab[ix.x + lane];                             \
            const uint32_t u1 = s_tab[ix.y + lane];                             \
            const uint32_t u2 = s_tab[ix.z + lane];                             \
            const uint32_t u3 = s_tab[ix.w + lane];                             \
            const uint32_t sm4 = (u0 + u1) + (u2 + u3); /* byte sums <= 4 */    \
            const uint32_t pm4 = __shfl_up_sync(0xffffffffu, sm4, 1);           \
            V0 = __dp4a((int)sm4, 0x00000001, -2);                              \
            V1 = __dp4a((int)sm4, 0x00000100, -2);                              \
            V2 = __dp4a((int)sm4, 0x00010000, -2);                              \
            V3 = __dp4a((int)sm4, 0x01000000, -2);                              \
            const int n3 = __dp4a((int)pm4, 0x01000000, -2);                    \
            const int n2 = __dp4a((int)pm4, 0x00010000, -2);                    \
            S1X = n3; S1Y = V0; S1Z = V1; S1W = V2;                             \
            S2X = n2; S2Y = n3; S2Z = V0; S2W = V1;                             \
        }

        {   /* warm-up rows t0, t0+1 (local idx) */
            int v0,v1,v2,v3, d1x,d1y,d1z,d1w;
            NG_STEP(t0 - tb,     v0,v1,v2,v3, d1x,d1y,d1z,d1w, a2x,a2y,a2z,a2w);
            NG_STEP(t0 - tb + 1, v0,v1,v2,v3, b1x,b1y,b1z,b1w, b2x,b2y,b2z,b2w);
        }

#pragma unroll 2
        for (int li = t0 - tb + 2; li < i1 - tb + 2; ++li) {
            int v0,v1,v2,v3, c1x,c1y,c1z,c1w, c2x,c2y,c2z,c2w;
            NG_STEP(li, v0,v1,v2,v3, c1x,c1y,c1z,c1w, c2x,c2y,c2z,c2w);
            ax += a2x * b1x * v0;
            ay += a2y * b1y * v1;
            az += a2z * b1z * v2;
            aw += a2w * b1w * v3;
            a2x = b2x; a2y = b2y; a2z = b2z; a2w = b2w;
            b2x = c2x; b2y = c2y; b2z = c2z; b2w = c2w;
            b1x = c1x; b1y = c1y; b1z = c1z; b1w = c1w;
        }
#undef NG_STEP

        atomicAdd(&s_acc[4*lane + 0], ax);
        atomicAdd(&s_acc[4*lane + 1], ay);
        atomicAdd(&s_acc[4*lane + 2], az);
        atomicAdd(&s_acc[4*lane + 3], aw);
    }

    __syncthreads();
    if (tid >= 2 && tid < 126) {
        int o = g * 124 + tid;
        if (o <= D_DIM + 1) {                /* dedupe wrap overlap */
            if (o >= D_DIM) o -= D_DIM;
            atomicAdd(&g_sample[o], (float)(s_acc[tid] * 8));
        }
    }
}

/* ---------- kernel 3: comb precompute (runs concurrently on stream 2) ---------- */
__global__ void __launch_bounds__(256) k_combine(const float* __restrict__ feat,
                                                 const float* __restrict__ feat_w,
                                                 const float* __restrict__ feat_b,
                                                 const float* __restrict__ mfcc_w,
                                                 const float* __restrict__ mfcc_b)
{
    __shared__ float s_feat[600];
    __shared__ float s_fh[8][32];
    const int tid = threadIdx.x;
    for (int i = tid; i < 600; i += 256) s_feat[i] = feat[i];
    __syncthreads();

    const int warpId = tid >> 5;
    const int lane   = tid & 31;
    const int d      = blockIdx.x * 8 + warpId;
    if (d >= D_DIM) return;

    /* batched loads: ~26 LDGs in flight before any reduction */
    float w0[6], w1[6], w2[6], bias[6];
#pragma unroll
    for (int k = 0; k < 6; ++k) {
        const float* wrow = mfcc_w + (k * D_DIM + d) * 91;
        w0[k]   = wrow[lane];
        w1[k]   = wrow[32 + lane];
        w2[k]   = (lane < 27) ? wrow[64 + lane] : 0.0f;
        bias[k] = mfcc_b[k * D_DIM + d];
    }
    float fwv = 0.0f, fbv = 0.0f, sv = 0.0f;
    if (lane < 29) {
        fwv = feat_w[lane * D_DIM + d];
        fbv = feat_b[lane * D_DIM + d];
        sv  = s_feat[c_featIdx[lane]];
    }

    float prod = 1.0f;
#pragma unroll
    for (int k = 0; k < 6; ++k) {
        float a = w0[k] * s_feat[k * 91 + lane]
                + w1[k] * s_feat[k * 91 + 32 + lane]
                + w2[k] * s_feat[k * 91 + 64 + ((lane < 27) ? lane : 0)];
#pragma unroll
        for (int off = 16; off; off >>= 1) a += __shfl_xor_sync(0xffffffffu, a, off);
        prod *= cosf(a + bias[k]) * sinf(a);
    }

    float fh = 0.0f;
    if (lane < 29) {
        const float pw = sv * fwv;
        fh = cosf(pw + fbv) * sinf(pw);
    }
    s_fh[warpId][lane] = fh;
    __syncwarp();

    if (lane == 0) {
        const float* f = s_fh[warpId];
        g_comb[d] =
              f[0]  * f[8]  * f[13]
            + f[1]  * f[9]  * f[14]
            + f[2]  * f[10] * f[15]
            + f[3]  * f[4]
            + f[5]  * f[7]  * f[22] * f[6]  * f[23] * f[19] * f[18]
                    * f[20] * f[21] * f[26] * f[28] * f[27]
            + f[11] + f[12]
            + f[16] * f[24]
            + f[17] + f[25]
            + prod;
    }
}

/* ---------- kernel 4: final bind + hard quantize ---------- */
__global__ void __launch_bounds__(256) k_sign(float* __restrict__ out)
{
    const int d = blockIdx.x * 256 + threadIdx.x;
    if (d < D_DIM)
        out[d] = (g_sample[d] * g_comb[d] > 0.0f) ? 1.0f : -1.0f;
}

/* ---------- launcher: fork combine onto a side stream, join before sign ---------- */
extern "C" void kernel_launch(void* const* d_in, const int* in_sizes, int n_in,
                              void* d_out, int out_size)
{
    (void)in_sizes; (void)n_in; (void)out_size;
    const float* signals = (const float*)d_in[0];
    const float* feat    = (const float*)d_in[1];
    const float* keys    = (const float*)d_in[2];
    const float* lw      = (const float*)d_in[3];
    const float* fw      = (const float*)d_in[4];
    const float* fb      = (const float*)d_in[5];
    const float* mw      = (const float*)d_in[6];
    const float* mb      = (const float*)d_in[7];
    float* out = (float*)d_out;

    static cudaStream_t s2 = nullptr;
    static cudaEvent_t  evFork = nullptr, evJoin = nullptr;
    if (!s2) {   /* created on the (uncaptured) correctness call, reused under capture */
        cudaStreamCreateWithFlags(&s2, cudaStreamNonBlocking);
        cudaEventCreateWithFlags(&evFork, cudaEventDisableTiming);
        cudaEventCreateWithFlags(&evJoin, cudaEventDisableTiming);
        cudaFuncSetAttribute(k_ngram, cudaFuncAttributeMaxDynamicSharedMemorySize, NG_SMEM);
    }

    cudaEventRecord(evFork, 0);
    cudaStreamWaitEvent(s2, evFork, 0);
    k_combine<<<1250, 256, 0, s2>>>(feat, fw, fb, mw, mb);
    cudaEventRecord(evJoin, s2);

    k_init<<<TABW_BLOCKS + AUX_BLOCKS, 256>>>(signals, keys, lw);
    k_ngram<<<GROUPS * SSPLIT, 512, NG_SMEM>>>();

    cudaStreamWaitEvent(0, evJoin, 0);
    k_sign<<<40, 256>>>(out);
}

// round 7
// speedup vs baseline: 1.6246x; 1.6246x over previous
#include <cuda_runtime.h>
#include <stdint.h>

#define D_DIM   10000
#define T_STEPS 2048
#define TN      2046            /* ngram terms */
#define GROUPS  81              /* column groups, stride 124, window 128 */
#define SSPLIT  5               /* t-splits per group */
#define TCHUNK  410             /* ceil(2046/5) */
#define WCH     26              /* ceil(410/16) steps per warp */
#define IDXN    412             /* staged idx entries per block */

/* smem words: s_tab 12800 | s_keys 128 | s_acc 128 | s_idx IDXN*4 */
#define NG_WORDS (12800 + 128 + 128 + IDXN * 4)
#define NG_SMEM  (NG_WORDS * 4)

__device__ float g_sample[D_DIM];
__device__ int   g_count[D_DIM];
__device__ float g_comb[D_DIM];

__constant__ int c_featIdx[29] = {
    546,547,548,550,553,555,556,557,558,559,560,561,562,564,
    565,566,569,575,579,580,581,582,583,584,587,592,597,598,599
};

/* ---------- kernel 1: comb precompute + zero accumulators/counters ---------- */
__global__ void __launch_bounds__(256) k_combine(const float* __restrict__ feat,
                                                 const float* __restrict__ feat_w,
                                                 const float* __restrict__ feat_b,
                                                 const float* __restrict__ mfcc_w,
                                                 const float* __restrict__ mfcc_b)
{
    __shared__ float s_feat[600];
    __shared__ float s_fh[8][32];
    const int tid = threadIdx.x;

    /* zero the ngram accumulators / completion counters for this block's 8 d's */
    const int zb = blockIdx.x * 8;
    if (tid < 8)            g_sample[zb + tid] = 0.0f;
    else if (tid < 16)      g_count[zb + tid - 8] = 0;

    for (int i = tid; i < 600; i += 256) s_feat[i] = feat[i];
    __syncthreads();

    const int warpId = tid >> 5;
    const int lane   = tid & 31;
    const int d      = blockIdx.x * 8 + warpId;
    if (d >= D_DIM) return;

    /* batched loads: ~26 LDGs in flight before any reduction */
    float w0[6], w1[6], w2[6], bias[6];
#pragma unroll
    for (int k = 0; k < 6; ++k) {
        const float* wrow = mfcc_w + (k * D_DIM + d) * 91;
        w0[k]   = wrow[lane];
        w1[k]   = wrow[32 + lane];
        w2[k]   = (lane < 27) ? wrow[64 + lane] : 0.0f;
        bias[k] = mfcc_b[k * D_DIM + d];
    }
    float fwv = 0.0f, fbv = 0.0f, sv = 0.0f;
    if (lane < 29) {
        fwv = feat_w[lane * D_DIM + d];
        fbv = feat_b[lane * D_DIM + d];
        sv  = s_feat[c_featIdx[lane]];
    }

    float prod = 1.0f;
#pragma unroll
    for (int k = 0; k < 6; ++k) {
        float a = w0[k] * s_feat[k * 91 + lane]
                + w1[k] * s_feat[k * 91 + 32 + lane]
                + w2[k] * s_feat[k * 91 + 64 + ((lane < 27) ? lane : 0)];
#pragma unroll
        for (int off = 16; off; off >>= 1) a += __shfl_xor_sync(0xffffffffu, a, off);
        prod *= cosf(a + bias[k]) * sinf(a);
    }

    float fh = 0.0f;
    if (lane < 29) {
        const float pw = sv * fwv;
        fh = cosf(pw + fbv) * sinf(pw);
    }
    s_fh[warpId][lane] = fh;
    __syncwarp();

    if (lane == 0) {
        const float* f = s_fh[warpId];
        g_comb[d] =
              f[0]  * f[8]  * f[13]
            + f[1]  * f[9]  * f[14]
            + f[2]  * f[10] * f[15]
            + f[3]  * f[4]
            + f[5]  * f[7]  * f[22] * f[6]  * f[23] * f[19] * f[18]
                    * f[20] * f[21] * f[26] * f[28] * f[27]
            + f[11] + f[12]
            + f[16] * f[24]
            + f[17] + f[25]
            + prod;
    }
}

/* ---------- kernel 2: self-contained ngram + fused hard-quantize ---------- */
__global__ void __launch_bounds__(512) k_ngram(const float* __restrict__ signals,
                                               const float* __restrict__ keys,
                                               const float* __restrict__ lw,
                                               float* __restrict__ out)
{
    extern __shared__ uint32_t smem[];
    uint32_t* s_tab  = smem;                      /* 12800 words: (c*100+l)*32+wd */
    uint32_t* s_keys = smem + 12800;              /* 128 words: c*32+wd */
    int*      s_acc  = (int*)(smem + 12928);      /* 128 accumulators */
    uint4*    s_idx  = (uint4*)(smem + 13056);    /* IDXN entries */

    const int tid  = threadIdx.x;
    const int g    = blockIdx.x / SSPLIT;
    const int s    = blockIdx.x % SSPLIT;
    const int col0 = g * 124;                     /* window start column */
    const int tb   = s * TCHUNK;

    /* key sign words ({0,1} bytes; 1 = positive) + zero acc */
    if (tid < 128) {
        const int c = tid >> 5, wd = tid & 31;
        int col = col0 + 4 * wd;
        if (col >= D_DIM) col -= D_DIM;           /* only group 80 wraps; 4-aligned */
        const float4 kf = *(const float4*)(keys + c * D_DIM + col);
        s_keys[tid] = ((~__float_as_uint(kf.x)) >> 31)
                    | (((~__float_as_uint(kf.y)) >> 31) << 8)
                    | (((~__float_as_uint(kf.z)) >> 31) << 16)
                    | (((~__float_as_uint(kf.w)) >> 31) << 24);
        s_acc[tid] = 0;
    }

    /* level indices for this block's t-range, computed from signals */
    if (tid < IDXN) {
        const int t = tb + tid;
        if (t < T_STEPS) {
            const float4 sg = *(const float4*)(signals + t * 4);
            float f0 = fminf(fmaxf(sg.x, 0.0f), 1.0f);
            float f1 = fminf(fmaxf(sg.y, 0.0f), 1.0f);
            float f2 = fminf(fmaxf(sg.z, 0.0f), 1.0f);
            float f3 = fminf(fmaxf(sg.w, 0.0f), 1.0f);
            int l0 = min(max((int)rintf(f0 * 99.0f), 0), 99);
            int l1 = min(max((int)rintf(f1 * 99.0f), 0), 99);
            int l2 = min(max((int)rintf(f2 * 99.0f), 0), 99);
            int l3 = min(max((int)rintf(f3 * 99.0f), 0), 99);
            s_idx[tid] = make_uint4(l0 * 32, 3200 + l1 * 32, 6400 + l2 * 32, 9600 + l3 * 32);
        }
    }
    __syncthreads();

    /* build sign table in SMEM: byte = 1 ^ (lw_sign ^ key_sign) */
    for (int wl = tid; wl < 3200; wl += 512) {
        const int l = wl >> 5, wd = wl & 31;
        int col = col0 + 4 * wd;
        if (col >= D_DIM) col -= D_DIM;
        const float4 wf = *(const float4*)(lw + l * D_DIM + col);
        const uint32_t ww = ((~__float_as_uint(wf.x)) >> 31)
                          | (((~__float_as_uint(wf.y)) >> 31) << 8)
                          | (((~__float_as_uint(wf.z)) >> 31) << 16)
                          | (((~__float_as_uint(wf.w)) >> 31) << 24);
        const uint32_t inv = ww ^ 0x01010101u;
#pragma unroll
        for (int c = 0; c < 4; ++c)
            s_tab[(c * 100 + l) * 32 + wd] = inv ^ s_keys[c * 32 + wd];
    }
    __syncthreads();

    const int warp = tid >> 5;
    const int lane = tid & 31;
    const int t0 = tb + warp * WCH;
    const int i1 = min(min(t0 + WCH, tb + TCHUNK), TN);

    if (t0 < i1) {
        int a2x, a2y, a2z, a2w;             /* s2 @ t-2 */
        int b2x, b2y, b2z, b2w;             /* s2 @ t-1 */
        int b1x, b1y, b1z, b1w;             /* s1 @ t-1 */
        int ax = 0, ay = 0, az = 0, aw = 0;

        /* per_t = 2s-4; carry v = s-2 (dp4a acc -2); x8 restored at writeback */
#define NG_STEP(LI, V0,V1,V2,V3, S1X,S1Y,S1Z,S1W, S2X,S2Y,S2Z,S2W)             \
        {                                                                       \
            const uint4 ix = s_idx[LI];                                         \
            const uint32_t u0 = s_tab[ix.x + lane];                             \
            const uint32_t u1 = s_tab[ix.y + lane];                             \
            const uint32_t u2 = s_tab[ix.z + lane];                             \
            const uint32_t u3 = s_tab[ix.w + lane];                             \
            const uint32_t sm4 = (u0 + u1) + (u2 + u3); /* byte sums <= 4 */    \
            const uint32_t pm4 = __shfl_up_sync(0xffffffffu, sm4, 1);           \
            V0 = __dp4a((int)sm4, 0x00000001, -2);                              \
            V1 = __dp4a((int)sm4, 0x00000100, -2);                              \
            V2 = __dp4a((int)sm4, 0x00010000, -2);                              \
            V3 = __dp4a((int)sm4, 0x01000000, -2);                              \
            const int n3 = __dp4a((int)pm4, 0x01000000, -2);                    \
            const int n2 = __dp4a((int)pm4, 0x00010000, -2);                    \
            S1X = n3; S1Y = V0; S1Z = V1; S1W = V2;                             \
            S2X = n2; S2Y = n3; S2Z = V0; S2W = V1;                             \
        }

        {   /* warm-up rows t0, t0+1 (local idx) */
            int v0,v1,v2,v3, d1x,d1y,d1z,d1w;
            NG_STEP(t0 - tb,     v0,v1,v2,v3, d1x,d1y,d1z,d1w, a2x,a2y,a2z,a2w);
            NG_STEP(t0 - tb + 1, v0,v1,v2,v3, b1x,b1y,b1z,b1w, b2x,b2y,b2z,b2w);
        }

#pragma unroll 2
        for (int li = t0 - tb + 2; li < i1 - tb + 2; ++li) {
            int v0,v1,v2,v3, c1x,c1y,c1z,c1w, c2x,c2y,c2z,c2w;
            NG_STEP(li, v0,v1,v2,v3, c1x,c1y,c1z,c1w, c2x,c2y,c2z,c2w);
            ax += a2x * b1x * v0;
            ay += a2y * b1y * v1;
            az += a2z * b1z * v2;
            aw += a2w * b1w * v3;
            a2x = b2x; a2y = b2y; a2z = b2z; a2w = b2w;
            b2x = c2x; b2y = c2y; b2z = c2z; b2w = c2w;
            b1x = c1x; b1y = c1y; b1z = c1z; b1w = c1w;
        }
#undef NG_STEP

        atomicAdd(&s_acc[4*lane + 0], ax);
        atomicAdd(&s_acc[4*lane + 1], ay);
        atomicAdd(&s_acc[4*lane + 2], az);
        atomicAdd(&s_acc[4*lane + 3], aw);
    }

    __syncthreads();
    /* window positions 2..125 -> global; 5th finisher per column quantizes */
    if (tid >= 2 && tid < 126) {
        int o = col0 + tid;
        if (o <= D_DIM + 1) {                /* dedupe wrap overlap */
            if (o >= D_DIM) o -= D_DIM;
            atomicAdd(&g_sample[o], (float)(s_acc[tid] * 8));
            __threadfence();
            if (atomicAdd(&g_count[o], 1) == SSPLIT - 1) {
                const float sv = atomicAdd(&g_sample[o], 0.0f) * g_comb[o];
                out[o] = (sv > 0.0f) ? 1.0f : -1.0f;
            }
        }
    }
}

/* ---------- launcher ---------- */
extern "C" void kernel_launch(void* const* d_in, const int* in_sizes, int n_in,
                              void* d_out, int out_size)
{
    (void)in_sizes; (void)n_in; (void)out_size;
    const float* signals = (const float*)d_in[0];
    const float* feat    = (const float*)d_in[1];
    const float* keys    = (const float*)d_in[2];
    const float* lw      = (const float*)d_in[3];
    const float* fw      = (const float*)d_in[4];
    const float* fb      = (const float*)d_in[5];
    const float* mw      = (const float*)d_in[6];
    const float* mb      = (const float*)d_in[7];
    float* out = (float*)d_out;

    static bool init = false;
    if (!init) {
        cudaFuncSetAttribute(k_ngram, cudaFuncAttributeMaxDynamicSharedMemorySize, NG_SMEM);
        init = true;
    }

    k_combine<<<1250, 256>>>(feat, fw, fb, mw, mb);
    k_ngram<<<GROUPS * SSPLIT, 512, NG_SMEM>>>(signals, keys, lw, out);
}